// round 12
// baseline (speedup 1.0000x reference)
#include <cuda_runtime.h>
#include <cuda_bf16.h>
#include <math.h>
#include <stdint.h>

// Problem constants
#define BB 256
#define TT 512
#define DD 512
#define HH 256
#define MM (BB * TT)   // 131072 rows

#define NEG (-1.0e30f)

// Scratch
__device__ float         g_em[MM * 3];        // emissions row-major [m][3]
__device__ __nv_bfloat16 g_W1T[HH * DD];      // W1 transposed -> bf16 [n][k]

// ---------------------------------------------------------------------------
// helpers
// ---------------------------------------------------------------------------
__device__ __forceinline__ unsigned pack_bf16(float lo, float hi) {
    unsigned d;
    asm("cvt.rn.bf16x2.f32 %0, %1, %2;" : "=r"(d) : "f"(hi), "f"(lo));
    return d;
}

__device__ __forceinline__ void mma_bf16(float (&d)[4],
                                         const unsigned (&a)[4],
                                         const unsigned b0, const unsigned b1) {
    asm volatile(
        "mma.sync.aligned.m16n8k16.row.col.f32.bf16.bf16.f32 "
        "{%0,%1,%2,%3}, {%4,%5,%6,%7}, {%8,%9}, {%0,%1,%2,%3};\n"
        : "+f"(d[0]), "+f"(d[1]), "+f"(d[2]), "+f"(d[3])
        : "r"(a[0]), "r"(a[1]), "r"(a[2]), "r"(a[3]),
          "r"(b0), "r"(b1));
}

__device__ __forceinline__ void ldsm_x4(unsigned& r0, unsigned& r1,
                                        unsigned& r2, unsigned& r3,
                                        uint32_t addr) {
    asm volatile("ldmatrix.sync.aligned.m8n8.x4.shared.b16 {%0,%1,%2,%3}, [%4];"
                 : "=r"(r0), "=r"(r1), "=r"(r2), "=r"(r3) : "r"(addr));
}

#define CP_ASYNC16(dst, src) \
    asm volatile("cp.async.cg.shared.global [%0], [%1], 16;\n" :: "r"(dst), "l"(src))
#define CP_COMMIT() asm volatile("cp.async.commit_group;\n")
#define CP_WAIT(n)  asm volatile("cp.async.wait_group %0;\n" :: "n"(n))

// Geometry: K-chunk 32.
// B (bf16, cp.async, 4-slot ring): 256 rows x 16 words + 4 pad = 20 words/row.
// A (bf16, LDG->cvt->STS, 4 static buffers): 64 rows x 20 words/row.
#define B_ROWW 20
#define B_ST_WORDS (256 * B_ROWW)            // 5120 words / slot
#define B_TOTAL_WORDS (4 * B_ST_WORDS)       // 20480
#define A_ROWW 20
#define A_BUF_WORDS (64 * A_ROWW)            // 1280 words / buffer
#define DYN_SMEM_BYTES ((B_TOTAL_WORDS + 4 * A_BUF_WORDS) * 4)   // 102400

// ---------------------------------------------------------------------------
// prep: W1 [D][H] f32 -> g_W1T [H][D] bf16 ; zero out[0]
// ---------------------------------------------------------------------------
__global__ void prep_kernel(const float* __restrict__ W1, float* out) {
    __shared__ float tile[32][33];
    const int k0 = blockIdx.x * 32;
    const int n0 = blockIdx.y * 32;
    if (blockIdx.x == 0 && blockIdx.y == 0 && threadIdx.x == 0 && threadIdx.y == 0)
        out[0] = 0.0f;
    tile[threadIdx.y][threadIdx.x] = W1[(size_t)(k0 + threadIdx.y) * HH + n0 + threadIdx.x];
    __syncthreads();
    g_W1T[(size_t)(n0 + threadIdx.y) * DD + k0 + threadIdx.x] =
        __float2bfloat16(tile[threadIdx.x][threadIdx.y]);
}

// ---------------------------------------------------------------------------
// Kernel 1: fused  em = gelu(x @ W1 + b1) @ W2 + b2   via bf16 m16n8k16.
// Block 256 thr (8 warps), BM=64, BN=256, BK=32, ldmatrix fragments.
// 2 chunks per barrier (8 barriers/block).
// CORRECT ordering (fixes R11 race): CP_WAIT(0) -> __syncthreads -> issue
// next-phase cp.async -> compute. The barrier AFTER the wait is what makes
// all threads' cp.async retirements visible block-wide (wait_group is
// per-thread state only).
// ---------------------------------------------------------------------------
__global__ __launch_bounds__(256, 2)
void fused_mlp_bf16(const float* __restrict__ x,
                    const float* __restrict__ b1,
                    const float* __restrict__ W2,
                    const float* __restrict__ b2)
{
    extern __shared__ uint32_t dsm[];
    uint32_t* bsm = dsm;                      // B ring: 4 x 5120 words
    uint32_t* abuf0 = dsm + B_TOTAL_WORDS;    // A buffers, static
    uint32_t* abuf1 = abuf0 + A_BUF_WORDS;
    uint32_t* abuf2 = abuf1 + A_BUF_WORDS;
    uint32_t* abuf3 = abuf2 + A_BUF_WORDS;

    __shared__ float s_w2[256][3];
    __shared__ float s_b1[256];
    __shared__ float em_s[64][3];

    const int tid  = threadIdx.x;
    const int wid  = tid >> 5;
    const int lane = tid & 31;
    const int g    = lane >> 2;
    const int c    = lane & 3;
    const int row_base = blockIdx.x * 64;
    const int cw   = wid * 32;

    s_b1[tid]    = b1[tid];
    s_w2[tid][0] = W2[tid * 3 + 0];
    s_w2[tid][1] = W2[tid * 3 + 1];
    s_w2[tid][2] = W2[tid * 3 + 2];
    if (tid < 192) ((float*)em_s)[tid] = 0.0f;

    // per-lane ldmatrix address offsets (in words)
    const int lm  = lane >> 3;    // matrix id 0..3
    const int lr  = lane & 7;     // row within matrix
    const int aoff = ((lm & 1) * 8 + lr) * A_ROWW + (lm >> 1) * 4;
    const int boff = ((lm >> 1) * 8 + lr) * B_ROWW + (lm & 1) * 4;

    const uint32_t a_sm0 = (uint32_t)__cvta_generic_to_shared(abuf0) + aoff * 4;
    const uint32_t a_sm1 = a_sm0 + A_BUF_WORDS * 4;
    const uint32_t a_sm2 = a_sm1 + A_BUF_WORDS * 4;
    const uint32_t a_sm3 = a_sm2 + A_BUF_WORDS * 4;
    const uint32_t b_sm  = (uint32_t)__cvta_generic_to_shared(bsm) +
                           (cw * B_ROWW + boff) * 4;

    float acc[4][4][4];
    #pragma unroll
    for (int mt = 0; mt < 4; ++mt)
        #pragma unroll
        for (int nt = 0; nt < 4; ++nt)
            #pragma unroll
            for (int e = 0; e < 4; ++e) acc[mt][nt][e] = 0.0f;

    // ---- A chunk loader (LDG f32 -> regs -> cvt -> STS bf16) ----
    const int ar0 = tid >> 3,           ach0 = tid & 7;
    const int ar1 = (tid + 256) >> 3,   ach1 = (tid + 256) & 7;
    auto ldgA = [&](float4& v0, float4& v1, int k0) {
        v0 = *(const float4*)&x[(size_t)(row_base + ar0) * DD + k0 + ach0 * 4];
        v1 = *(const float4*)&x[(size_t)(row_base + ar1) * DD + k0 + ach1 * 4];
    };
    auto stsA = [&](uint32_t* ab, const float4& v0, const float4& v1) {
        uint2 w0 = make_uint2(pack_bf16(v0.x, v0.y), pack_bf16(v0.z, v0.w));
        uint2 w1 = make_uint2(pack_bf16(v1.x, v1.y), pack_bf16(v1.z, v1.w));
        *(uint2*)&ab[ar0 * A_ROWW + ach0 * 2] = w0;
        *(uint2*)&ab[ar1 * A_ROWW + ach1 * 2] = w1;
    };

    // ---- B slot loader (no commit; caller commits per phase) ----
    auto issueB = [&](int slot, int k0) {
        const uint32_t base = (uint32_t)__cvta_generic_to_shared(bsm) +
                              slot * (B_ST_WORDS * 4);
        #pragma unroll
        for (int i = 0; i < 4; ++i) {
            const int id = tid + i * 256;
            const int n = id >> 2, j = id & 3;
            CP_ASYNC16(base + n * (B_ROWW * 4) + j * 16,
                       &g_W1T[(size_t)n * DD + k0 + j * 8]);
        }
    };

    // ---- compute one chunk: A frag base addr + static B slot ----
    auto compute = [&](uint32_t a_base, int bslot) {
        const uint32_t bb = b_sm + bslot * (B_ST_WORDS * 4);
        #pragma unroll
        for (int ks = 0; ks < 2; ++ks) {
            const uint32_t kw4 = ks * 8 * 4;
            unsigned bf[4][2];
            ldsm_x4(bf[0][0], bf[0][1], bf[1][0], bf[1][1], bb + kw4);
            ldsm_x4(bf[2][0], bf[2][1], bf[3][0], bf[3][1],
                    bb + 16 * (B_ROWW * 4) + kw4);
            #pragma unroll
            for (int mt = 0; mt < 4; ++mt) {
                unsigned af[4];
                ldsm_x4(af[0], af[1], af[2], af[3],
                        a_base + mt * 16 * (A_ROWW * 4) + kw4);
                #pragma unroll
                for (int nt = 0; nt < 4; ++nt)
                    mma_bf16(acc[mt][nt], af, bf[nt][0], bf[nt][1]);
            }
        }
    };

    // ---- prologue: chunks 0,1 into bufs/slots 0,1 ----
    float4 e0, e1, o0, o1;
    ldgA(e0, e1, 0);  ldgA(o0, o1, 32);
    stsA(abuf0, e0, e1);  stsA(abuf1, o0, o1);
    issueB(0, 0);  issueB(1, 32);
    CP_COMMIT();

    // ---- 4 super-iterations of 2 phases x 2 chunks ----
    #pragma unroll 1
    for (int s = 0; s < 4; ++s) {
        const int k4 = s * 4 * 32;

        // phase even: compute chunks 4s,4s+1 (bufs/slots 0,1); prefetch 4s+2,4s+3
        CP_WAIT(0);          // own groups drained (holds this phase's data)
        __syncthreads();     // publish ALL threads' retirements before reads
        ldgA(e0, e1, k4 + 2 * 32);  ldgA(o0, o1, k4 + 3 * 32);
        issueB(2, k4 + 2 * 32);  issueB(3, k4 + 3 * 32);
        CP_COMMIT();
        compute(a_sm0, 0);
        compute(a_sm1, 1);
        stsA(abuf2, e0, e1);  stsA(abuf3, o0, o1);

        // phase odd: compute chunks 4s+2,4s+3 (bufs/slots 2,3); prefetch 4s+4,4s+5
        CP_WAIT(0);
        __syncthreads();
        if (s < 3) {
            ldgA(e0, e1, k4 + 4 * 32);  ldgA(o0, o1, k4 + 5 * 32);
            issueB(0, k4 + 4 * 32);  issueB(1, k4 + 5 * 32);
            CP_COMMIT();
        }
        compute(a_sm2, 2);
        compute(a_sm3, 3);
        if (s < 3) { stsA(abuf0, e0, e1);  stsA(abuf1, o0, o1); }
    }

    // ---- epilogue: bias + exact gelu + W2 contraction ----
    float pem[8][3];
    #pragma unroll
    for (int i = 0; i < 8; ++i)
        #pragma unroll
        for (int k = 0; k < 3; ++k) pem[i][k] = 0.0f;

    #pragma unroll
    for (int mt = 0; mt < 4; ++mt)
        #pragma unroll
        for (int nt = 0; nt < 4; ++nt)
            #pragma unroll
            for (int e = 0; e < 4; ++e) {
                const int col = cw + nt * 8 + 2 * c + (e & 1);
                const int slot = mt * 2 + (e >> 1);
                const float v = acc[mt][nt][e] + s_b1[col];
                const float h = 0.5f * v * (1.0f + erff(v * 0.7071067811865476f));
                pem[slot][0] = fmaf(h, s_w2[col][0], pem[slot][0]);
                pem[slot][1] = fmaf(h, s_w2[col][1], pem[slot][1]);
                pem[slot][2] = fmaf(h, s_w2[col][2], pem[slot][2]);
            }

    #pragma unroll
    for (int d = 1; d < 4; d <<= 1)
        #pragma unroll
        for (int i = 0; i < 8; ++i)
            #pragma unroll
            for (int k = 0; k < 3; ++k)
                pem[i][k] += __shfl_xor_sync(0xffffffffu, pem[i][k], d);

    if (c == 0) {
        #pragma unroll
        for (int i = 0; i < 8; ++i) {
            const int row = (i >> 1) * 16 + g + (i & 1) * 8;
            atomicAdd(&em_s[row][0], pem[i][0]);
            atomicAdd(&em_s[row][1], pem[i][1]);
            atomicAdd(&em_s[row][2], pem[i][2]);
        }
    }
    __syncthreads();

    if (tid < 192) {
        g_em[(size_t)row_base * 3 + tid] = ((float*)em_s)[tid] + b2[tid % 3];
    }
}

// ---------------------------------------------------------------------------
// Kernel 2: CRF via log-semiring associative scan (unchanged, proven 12us).
// ---------------------------------------------------------------------------
__device__ __forceinline__ float sel3(float a, float b, float c, int i) {
    return (i == 0) ? a : ((i == 1) ? b : c);
}
__device__ __forceinline__ float lse3(float x, float y, float z) {
    const float m = fmaxf(fmaxf(x, y), z);
    return m + __logf(__expf(x - m) + __expf(y - m) + __expf(z - m));
}

#define CRF_WARPS 4

__global__ __launch_bounds__(32 * CRF_WARPS)
void crf_kernel(const int* __restrict__ tags,
                const int* __restrict__ lengths,
                const float* __restrict__ trans,
                const float* __restrict__ start,
                const float* __restrict__ end,
                float* __restrict__ out)
{
    __shared__ float s_em[CRF_WARPS][TT * 3];
    __shared__ int   s_tag[CRF_WARPS][TT];
    __shared__ float s_tr[9];

    const int wid  = threadIdx.x >> 5;
    const int lane = threadIdx.x & 31;
    const int b    = blockIdx.x * CRF_WARPS + wid;

    if (threadIdx.x < 9) s_tr[threadIdx.x] = trans[threadIdx.x];
    __syncthreads();

    {
        const float4* src = reinterpret_cast<const float4*>(&g_em[(size_t)b * TT * 3]);
        float4* dst = reinterpret_cast<float4*>(s_em[wid]);
        #pragma unroll
        for (int i = 0; i < 12; ++i) dst[lane + i * 32] = src[lane + i * 32];
        const int4* ts = reinterpret_cast<const int4*>(&tags[(size_t)b * TT]);
        int4* td = reinterpret_cast<int4*>(s_tag[wid]);
        #pragma unroll
        for (int i = 0; i < 4; ++i) td[lane + i * 32] = ts[lane + i * 32];
    }
    __syncwarp();

    const float t00 = s_tr[0], t01 = s_tr[1], t02 = s_tr[2];
    const float t10 = s_tr[3], t11 = s_tr[4], t12 = s_tr[5];
    const float t20 = s_tr[6], t21 = s_tr[7], t22 = s_tr[8];
    const float st0 = start[0], st1 = start[1], st2 = start[2];
    const float en0 = end[0],   en1 = end[1],   en2 = end[2];

    const int len = max(lengths[b], 1);
    const float* em = s_em[wid];
    const int*   tg = s_tag[wid];

    const int t0 = 1 + lane * 16;
    float M[3][3];
    if (t0 < len) {
        float e0 = em[t0 * 3 + 0], e1 = em[t0 * 3 + 1], e2 = em[t0 * 3 + 2];
        M[0][0] = t00 + e0; M[0][1] = t01 + e1; M[0][2] = t02 + e2;
        M[1][0] = t10 + e0; M[1][1] = t11 + e1; M[1][2] = t12 + e2;
        M[2][0] = t20 + e0; M[2][1] = t21 + e1; M[2][2] = t22 + e2;
        #pragma unroll 1
        for (int s = 1; s < 16; ++s) {
            const int t = t0 + s;
            if (t >= len) break;
            e0 = em[t * 3 + 0]; e1 = em[t * 3 + 1]; e2 = em[t * 3 + 2];
            float C[3][3];
            #pragma unroll
            for (int i = 0; i < 3; ++i) {
                C[i][0] = lse3(M[i][0] + t00, M[i][1] + t10, M[i][2] + t20) + e0;
                C[i][1] = lse3(M[i][0] + t01, M[i][1] + t11, M[i][2] + t21) + e1;
                C[i][2] = lse3(M[i][0] + t02, M[i][1] + t12, M[i][2] + t22) + e2;
            }
            #pragma unroll
            for (int i = 0; i < 3; ++i)
                #pragma unroll
                for (int k = 0; k < 3; ++k) M[i][k] = C[i][k];
        }
    } else {
        #pragma unroll
        for (int i = 0; i < 3; ++i)
            #pragma unroll
            for (int k = 0; k < 3; ++k) M[i][k] = (i == k) ? 0.0f : NEG;
    }

    float num = 0.0f;
    {
        int tp = tg[t0 - 1];
        #pragma unroll 1
        for (int s = 0; s < 16; ++s) {
            const int t = t0 + s;
            if (t >= len) break;
            const int tc = tg[t];
            num += s_tr[tp * 3 + tc] + em[t * 3 + tc];
            tp = tc;
        }
    }
    if (lane == 0) {
        const int tag0 = tg[0];
        num += sel3(st0, st1, st2, tag0) + sel3(em[0], em[1], em[2], tag0);
        if (len == 1) num += sel3(en0, en1, en2, tag0);
    }
    {
        const int tl = len - 1;
        if (tl >= t0 && tl < t0 + 16) num += sel3(en0, en1, en2, tg[tl]);
    }

    #pragma unroll
    for (int off = 1; off < 32; off <<= 1) {
        float O[3][3];
        #pragma unroll
        for (int i = 0; i < 3; ++i)
            #pragma unroll
            for (int k = 0; k < 3; ++k)
                O[i][k] = __shfl_xor_sync(0xffffffffu, M[i][k], off);
        const bool lower = ((lane & off) == 0);
        float L[3][3], R[3][3];
        #pragma unroll
        for (int i = 0; i < 3; ++i)
            #pragma unroll
            for (int k = 0; k < 3; ++k) {
                L[i][k] = lower ? M[i][k] : O[i][k];
                R[i][k] = lower ? O[i][k] : M[i][k];
            }
        #pragma unroll
        for (int i = 0; i < 3; ++i)
            #pragma unroll
            for (int k = 0; k < 3; ++k)
                M[i][k] = lse3(L[i][0] + R[0][k], L[i][1] + R[1][k], L[i][2] + R[2][k]);
    }

    #pragma unroll
    for (int off = 16; off > 0; off >>= 1)
        num += __shfl_xor_sync(0xffffffffu, num, off);

    if (lane == 0) {
        const float a00 = st0 + em[0];
        const float a01 = st1 + em[1];
        const float a02 = st2 + em[2];
        float aT[3];
        #pragma unroll
        for (int k = 0; k < 3; ++k)
            aT[k] = lse3(a00 + M[0][k], a01 + M[1][k], a02 + M[2][k]);
        const float denom = lse3(aT[0] + en0, aT[1] + en1, aT[2] + en2);
        atomicAdd(out, -(num - denom) * (1.0f / (float)BB));
    }
}

// ---------------------------------------------------------------------------
extern "C" void kernel_launch(void* const* d_in, const int* in_sizes, int n_in,
                              void* d_out, int out_size)
{
    const float* x       = (const float*)d_in[0];
    const int*   tags    = (const int*)  d_in[1];
    const int*   lengths = (const int*)  d_in[2];
    const float* W1      = (const float*)d_in[3];
    const float* b1      = (const float*)d_in[4];
    const float* W2      = (const float*)d_in[5];
    const float* b2      = (const float*)d_in[6];
    const float* trans   = (const float*)d_in[7];
    const float* start   = (const float*)d_in[8];
    const float* end     = (const float*)d_in[9];

    cudaFuncSetAttribute(fused_mlp_bf16,
                         cudaFuncAttributeMaxDynamicSharedMemorySize,
                         DYN_SMEM_BYTES);

    prep_kernel<<<dim3(DD / 32, HH / 32), dim3(32, 32)>>>(W1, (float*)d_out);
    fused_mlp_bf16<<<MM / 64, 256, DYN_SMEM_BYTES>>>(x, b1, W2, b2);
    crf_kernel<<<BB / CRF_WARPS, 32 * CRF_WARPS>>>(tags, lengths, trans, start, end,
                                                   (float*)d_out);
}

// round 13
// speedup vs baseline: 1.0005x; 1.0005x over previous
#include <cuda_runtime.h>
#include <cuda_bf16.h>
#include <math.h>
#include <stdint.h>

// Problem constants
#define BB 256
#define TT 512
#define DD 512
#define HH 256
#define MM (BB * TT)   // 131072 rows

#define NEG (-1.0e30f)

// Scratch
__device__ float         g_em[MM * 3];        // emissions row-major [m][3]
__device__ __nv_bfloat16 g_W1T[HH * DD];      // W1 transposed -> bf16 [n][k]

// ---------------------------------------------------------------------------
// helpers
// ---------------------------------------------------------------------------
__device__ __forceinline__ unsigned pack_bf16(float lo, float hi) {
    unsigned d;
    asm("cvt.rn.bf16x2.f32 %0, %1, %2;" : "=r"(d) : "f"(hi), "f"(lo));
    return d;
}

__device__ __forceinline__ void mma_bf16(float (&d)[4],
                                         const unsigned (&a)[4],
                                         const unsigned b0, const unsigned b1) {
    asm volatile(
        "mma.sync.aligned.m16n8k16.row.col.f32.bf16.bf16.f32 "
        "{%0,%1,%2,%3}, {%4,%5,%6,%7}, {%8,%9}, {%0,%1,%2,%3};\n"
        : "+f"(d[0]), "+f"(d[1]), "+f"(d[2]), "+f"(d[3])
        : "r"(a[0]), "r"(a[1]), "r"(a[2]), "r"(a[3]),
          "r"(b0), "r"(b1));
}

__device__ __forceinline__ void ldsm_x4(unsigned& r0, unsigned& r1,
                                        unsigned& r2, unsigned& r3,
                                        uint32_t addr) {
    asm volatile("ldmatrix.sync.aligned.m8n8.x4.shared.b16 {%0,%1,%2,%3}, [%4];"
                 : "=r"(r0), "=r"(r1), "=r"(r2), "=r"(r3) : "r"(addr));
}

#define CP_ASYNC16(dst, src) \
    asm volatile("cp.async.cg.shared.global [%0], [%1], 16;\n" :: "r"(dst), "l"(src))
#define CP_COMMIT() asm volatile("cp.async.commit_group;\n")
#define CP_WAIT(n)  asm volatile("cp.async.wait_group %0;\n" :: "n"(n))

// Geometry: K-chunk 32.
// B (bf16, cp.async, 4-slot ring): 256 rows x 16 words + 4 pad = 20 words/row.
// A (bf16, LDG->cvt->STS, 4 static buffers): 64 rows x 20 words/row.
#define B_ROWW 20
#define B_ST_WORDS (256 * B_ROWW)            // 5120 words / slot
#define B_TOTAL_WORDS (4 * B_ST_WORDS)       // 20480
#define A_ROWW 20
#define A_BUF_WORDS (64 * A_ROWW)            // 1280 words / buffer
#define DYN_SMEM_BYTES ((B_TOTAL_WORDS + 4 * A_BUF_WORDS) * 4)   // 102400

// ---------------------------------------------------------------------------
// prep: W1 [D][H] f32 -> g_W1T [H][D] bf16 ; zero out[0]
// ---------------------------------------------------------------------------
__global__ void prep_kernel(const float* __restrict__ W1, float* out) {
    __shared__ float tile[32][33];
    const int k0 = blockIdx.x * 32;
    const int n0 = blockIdx.y * 32;
    if (blockIdx.x == 0 && blockIdx.y == 0 && threadIdx.x == 0 && threadIdx.y == 0)
        out[0] = 0.0f;
    tile[threadIdx.y][threadIdx.x] = W1[(size_t)(k0 + threadIdx.y) * HH + n0 + threadIdx.x];
    __syncthreads();
    g_W1T[(size_t)(n0 + threadIdx.y) * DD + k0 + threadIdx.x] =
        __float2bfloat16(tile[threadIdx.x][threadIdx.y]);
}

// ---------------------------------------------------------------------------
// Kernel 1: fused  em = gelu(x @ W1 + b1) @ W2 + b2   via bf16 m16n8k16.
// Block 256 thr (8 warps), BM=64, BN=256, BK=32, ldmatrix fragments.
// 2 chunks per barrier (8 barriers/block).
// CORRECT ordering (fixes R11 race): CP_WAIT(0) -> __syncthreads -> issue
// next-phase cp.async -> compute. The barrier AFTER the wait is what makes
// all threads' cp.async retirements visible block-wide (wait_group is
// per-thread state only).
// ---------------------------------------------------------------------------
__global__ __launch_bounds__(256, 2)
void fused_mlp_bf16(const float* __restrict__ x,
                    const float* __restrict__ b1,
                    const float* __restrict__ W2,
                    const float* __restrict__ b2)
{
    extern __shared__ uint32_t dsm[];
    uint32_t* bsm = dsm;                      // B ring: 4 x 5120 words
    uint32_t* abuf0 = dsm + B_TOTAL_WORDS;    // A buffers, static
    uint32_t* abuf1 = abuf0 + A_BUF_WORDS;
    uint32_t* abuf2 = abuf1 + A_BUF_WORDS;
    uint32_t* abuf3 = abuf2 + A_BUF_WORDS;

    __shared__ float s_w2[256][3];
    __shared__ float s_b1[256];
    __shared__ float em_s[64][3];

    const int tid  = threadIdx.x;
    const int wid  = tid >> 5;
    const int lane = tid & 31;
    const int g    = lane >> 2;
    const int c    = lane & 3;
    const int row_base = blockIdx.x * 64;
    const int cw   = wid * 32;

    s_b1[tid]    = b1[tid];
    s_w2[tid][0] = W2[tid * 3 + 0];
    s_w2[tid][1] = W2[tid * 3 + 1];
    s_w2[tid][2] = W2[tid * 3 + 2];
    if (tid < 192) ((float*)em_s)[tid] = 0.0f;

    // per-lane ldmatrix address offsets (in words)
    const int lm  = lane >> 3;    // matrix id 0..3
    const int lr  = lane & 7;     // row within matrix
    const int aoff = ((lm & 1) * 8 + lr) * A_ROWW + (lm >> 1) * 4;
    const int boff = ((lm >> 1) * 8 + lr) * B_ROWW + (lm & 1) * 4;

    const uint32_t a_sm0 = (uint32_t)__cvta_generic_to_shared(abuf0) + aoff * 4;
    const uint32_t a_sm1 = a_sm0 + A_BUF_WORDS * 4;
    const uint32_t a_sm2 = a_sm1 + A_BUF_WORDS * 4;
    const uint32_t a_sm3 = a_sm2 + A_BUF_WORDS * 4;
    const uint32_t b_sm  = (uint32_t)__cvta_generic_to_shared(bsm) +
                           (cw * B_ROWW + boff) * 4;

    float acc[4][4][4];
    #pragma unroll
    for (int mt = 0; mt < 4; ++mt)
        #pragma unroll
        for (int nt = 0; nt < 4; ++nt)
            #pragma unroll
            for (int e = 0; e < 4; ++e) acc[mt][nt][e] = 0.0f;

    // ---- A chunk loader (LDG f32 -> regs -> cvt -> STS bf16) ----
    const int ar0 = tid >> 3,           ach0 = tid & 7;
    const int ar1 = (tid + 256) >> 3,   ach1 = (tid + 256) & 7;
    auto ldgA = [&](float4& v0, float4& v1, int k0) {
        v0 = *(const float4*)&x[(size_t)(row_base + ar0) * DD + k0 + ach0 * 4];
        v1 = *(const float4*)&x[(size_t)(row_base + ar1) * DD + k0 + ach1 * 4];
    };
    auto stsA = [&](uint32_t* ab, const float4& v0, const float4& v1) {
        uint2 w0 = make_uint2(pack_bf16(v0.x, v0.y), pack_bf16(v0.z, v0.w));
        uint2 w1 = make_uint2(pack_bf16(v1.x, v1.y), pack_bf16(v1.z, v1.w));
        *(uint2*)&ab[ar0 * A_ROWW + ach0 * 2] = w0;
        *(uint2*)&ab[ar1 * A_ROWW + ach1 * 2] = w1;
    };

    // ---- B slot loader (no commit; caller commits per phase) ----
    auto issueB = [&](int slot, int k0) {
        const uint32_t base = (uint32_t)__cvta_generic_to_shared(bsm) +
                              slot * (B_ST_WORDS * 4);
        #pragma unroll
        for (int i = 0; i < 4; ++i) {
            const int id = tid + i * 256;
            const int n = id >> 2, j = id & 3;
            CP_ASYNC16(base + n * (B_ROWW * 4) + j * 16,
                       &g_W1T[(size_t)n * DD + k0 + j * 8]);
        }
    };

    // ---- compute one chunk: A frag base addr + static B slot ----
    auto compute = [&](uint32_t a_base, int bslot) {
        const uint32_t bb = b_sm + bslot * (B_ST_WORDS * 4);
        #pragma unroll
        for (int ks = 0; ks < 2; ++ks) {
            const uint32_t kw4 = ks * 8 * 4;
            unsigned bf[4][2];
            ldsm_x4(bf[0][0], bf[0][1], bf[1][0], bf[1][1], bb + kw4);
            ldsm_x4(bf[2][0], bf[2][1], bf[3][0], bf[3][1],
                    bb + 16 * (B_ROWW * 4) + kw4);
            #pragma unroll
            for (int mt = 0; mt < 4; ++mt) {
                unsigned af[4];
                ldsm_x4(af[0], af[1], af[2], af[3],
                        a_base + mt * 16 * (A_ROWW * 4) + kw4);
                #pragma unroll
                for (int nt = 0; nt < 4; ++nt)
                    mma_bf16(acc[mt][nt], af, bf[nt][0], bf[nt][1]);
            }
        }
    };

    // ---- prologue: chunks 0,1 into bufs/slots 0,1 ----
    float4 e0, e1, o0, o1;
    ldgA(e0, e1, 0);  ldgA(o0, o1, 32);
    stsA(abuf0, e0, e1);  stsA(abuf1, o0, o1);
    issueB(0, 0);  issueB(1, 32);
    CP_COMMIT();

    // ---- 4 super-iterations of 2 phases x 2 chunks ----
    #pragma unroll 1
    for (int s = 0; s < 4; ++s) {
        const int k4 = s * 4 * 32;

        // phase even: compute chunks 4s,4s+1 (bufs/slots 0,1); prefetch 4s+2,4s+3
        CP_WAIT(0);          // own groups drained (holds this phase's data)
        __syncthreads();     // publish ALL threads' retirements before reads
        ldgA(e0, e1, k4 + 2 * 32);  ldgA(o0, o1, k4 + 3 * 32);
        issueB(2, k4 + 2 * 32);  issueB(3, k4 + 3 * 32);
        CP_COMMIT();
        compute(a_sm0, 0);
        compute(a_sm1, 1);
        stsA(abuf2, e0, e1);  stsA(abuf3, o0, o1);

        // phase odd: compute chunks 4s+2,4s+3 (bufs/slots 2,3); prefetch 4s+4,4s+5
        CP_WAIT(0);
        __syncthreads();
        if (s < 3) {
            ldgA(e0, e1, k4 + 4 * 32);  ldgA(o0, o1, k4 + 5 * 32);
            issueB(0, k4 + 4 * 32);  issueB(1, k4 + 5 * 32);
            CP_COMMIT();
        }
        compute(a_sm2, 2);
        compute(a_sm3, 3);
        if (s < 3) { stsA(abuf0, e0, e1);  stsA(abuf1, o0, o1); }
    }

    // ---- epilogue: bias + exact gelu + W2 contraction ----
    float pem[8][3];
    #pragma unroll
    for (int i = 0; i < 8; ++i)
        #pragma unroll
        for (int k = 0; k < 3; ++k) pem[i][k] = 0.0f;

    #pragma unroll
    for (int mt = 0; mt < 4; ++mt)
        #pragma unroll
        for (int nt = 0; nt < 4; ++nt)
            #pragma unroll
            for (int e = 0; e < 4; ++e) {
                const int col = cw + nt * 8 + 2 * c + (e & 1);
                const int slot = mt * 2 + (e >> 1);
                const float v = acc[mt][nt][e] + s_b1[col];
                const float h = 0.5f * v * (1.0f + erff(v * 0.7071067811865476f));
                pem[slot][0] = fmaf(h, s_w2[col][0], pem[slot][0]);
                pem[slot][1] = fmaf(h, s_w2[col][1], pem[slot][1]);
                pem[slot][2] = fmaf(h, s_w2[col][2], pem[slot][2]);
            }

    #pragma unroll
    for (int d = 1; d < 4; d <<= 1)
        #pragma unroll
        for (int i = 0; i < 8; ++i)
            #pragma unroll
            for (int k = 0; k < 3; ++k)
                pem[i][k] += __shfl_xor_sync(0xffffffffu, pem[i][k], d);

    if (c == 0) {
        #pragma unroll
        for (int i = 0; i < 8; ++i) {
            const int row = (i >> 1) * 16 + g + (i & 1) * 8;
            atomicAdd(&em_s[row][0], pem[i][0]);
            atomicAdd(&em_s[row][1], pem[i][1]);
            atomicAdd(&em_s[row][2], pem[i][2]);
        }
    }
    __syncthreads();

    if (tid < 192) {
        g_em[(size_t)row_base * 3 + tid] = ((float*)em_s)[tid] + b2[tid % 3];
    }
}

// ---------------------------------------------------------------------------
// Kernel 2: CRF via log-semiring associative scan (unchanged, proven 12us).
// ---------------------------------------------------------------------------
__device__ __forceinline__ float sel3(float a, float b, float c, int i) {
    return (i == 0) ? a : ((i == 1) ? b : c);
}
__device__ __forceinline__ float lse3(float x, float y, float z) {
    const float m = fmaxf(fmaxf(x, y), z);
    return m + __logf(__expf(x - m) + __expf(y - m) + __expf(z - m));
}

#define CRF_WARPS 4

__global__ __launch_bounds__(32 * CRF_WARPS)
void crf_kernel(const int* __restrict__ tags,
                const int* __restrict__ lengths,
                const float* __restrict__ trans,
                const float* __restrict__ start,
                const float* __restrict__ end,
                float* __restrict__ out)
{
    __shared__ float s_em[CRF_WARPS][TT * 3];
    __shared__ int   s_tag[CRF_WARPS][TT];
    __shared__ float s_tr[9];

    const int wid  = threadIdx.x >> 5;
    const int lane = threadIdx.x & 31;
    const int b    = blockIdx.x * CRF_WARPS + wid;

    if (threadIdx.x < 9) s_tr[threadIdx.x] = trans[threadIdx.x];
    __syncthreads();

    {
        const float4* src = reinterpret_cast<const float4*>(&g_em[(size_t)b * TT * 3]);
        float4* dst = reinterpret_cast<float4*>(s_em[wid]);
        #pragma unroll
        for (int i = 0; i < 12; ++i) dst[lane + i * 32] = src[lane + i * 32];
        const int4* ts = reinterpret_cast<const int4*>(&tags[(size_t)b * TT]);
        int4* td = reinterpret_cast<int4*>(s_tag[wid]);
        #pragma unroll
        for (int i = 0; i < 4; ++i) td[lane + i * 32] = ts[lane + i * 32];
    }
    __syncwarp();

    const float t00 = s_tr[0], t01 = s_tr[1], t02 = s_tr[2];
    const float t10 = s_tr[3], t11 = s_tr[4], t12 = s_tr[5];
    const float t20 = s_tr[6], t21 = s_tr[7], t22 = s_tr[8];
    const float st0 = start[0], st1 = start[1], st2 = start[2];
    const float en0 = end[0],   en1 = end[1],   en2 = end[2];

    const int len = max(lengths[b], 1);
    const float* em = s_em[wid];
    const int*   tg = s_tag[wid];

    const int t0 = 1 + lane * 16;
    float M[3][3];
    if (t0 < len) {
        float e0 = em[t0 * 3 + 0], e1 = em[t0 * 3 + 1], e2 = em[t0 * 3 + 2];
        M[0][0] = t00 + e0; M[0][1] = t01 + e1; M[0][2] = t02 + e2;
        M[1][0] = t10 + e0; M[1][1] = t11 + e1; M[1][2] = t12 + e2;
        M[2][0] = t20 + e0; M[2][1] = t21 + e1; M[2][2] = t22 + e2;
        #pragma unroll 1
        for (int s = 1; s < 16; ++s) {
            const int t = t0 + s;
            if (t >= len) break;
            e0 = em[t * 3 + 0]; e1 = em[t * 3 + 1]; e2 = em[t * 3 + 2];
            float C[3][3];
            #pragma unroll
            for (int i = 0; i < 3; ++i) {
                C[i][0] = lse3(M[i][0] + t00, M[i][1] + t10, M[i][2] + t20) + e0;
                C[i][1] = lse3(M[i][0] + t01, M[i][1] + t11, M[i][2] + t21) + e1;
                C[i][2] = lse3(M[i][0] + t02, M[i][1] + t12, M[i][2] + t22) + e2;
            }
            #pragma unroll
            for (int i = 0; i < 3; ++i)
                #pragma unroll
                for (int k = 0; k < 3; ++k) M[i][k] = C[i][k];
        }
    } else {
        #pragma unroll
        for (int i = 0; i < 3; ++i)
            #pragma unroll
            for (int k = 0; k < 3; ++k) M[i][k] = (i == k) ? 0.0f : NEG;
    }

    float num = 0.0f;
    {
        int tp = tg[t0 - 1];
        #pragma unroll 1
        for (int s = 0; s < 16; ++s) {
            const int t = t0 + s;
            if (t >= len) break;
            const int tc = tg[t];
            num += s_tr[tp * 3 + tc] + em[t * 3 + tc];
            tp = tc;
        }
    }
    if (lane == 0) {
        const int tag0 = tg[0];
        num += sel3(st0, st1, st2, tag0) + sel3(em[0], em[1], em[2], tag0);
        if (len == 1) num += sel3(en0, en1, en2, tag0);
    }
    {
        const int tl = len - 1;
        if (tl >= t0 && tl < t0 + 16) num += sel3(en0, en1, en2, tg[tl]);
    }

    #pragma unroll
    for (int off = 1; off < 32; off <<= 1) {
        float O[3][3];
        #pragma unroll
        for (int i = 0; i < 3; ++i)
            #pragma unroll
            for (int k = 0; k < 3; ++k)
                O[i][k] = __shfl_xor_sync(0xffffffffu, M[i][k], off);
        const bool lower = ((lane & off) == 0);
        float L[3][3], R[3][3];
        #pragma unroll
        for (int i = 0; i < 3; ++i)
            #pragma unroll
            for (int k = 0; k < 3; ++k) {
                L[i][k] = lower ? M[i][k] : O[i][k];
                R[i][k] = lower ? O[i][k] : M[i][k];
            }
        #pragma unroll
        for (int i = 0; i < 3; ++i)
            #pragma unroll
            for (int k = 0; k < 3; ++k)
                M[i][k] = lse3(L[i][0] + R[0][k], L[i][1] + R[1][k], L[i][2] + R[2][k]);
    }

    #pragma unroll
    for (int off = 16; off > 0; off >>= 1)
        num += __shfl_xor_sync(0xffffffffu, num, off);

    if (lane == 0) {
        const float a00 = st0 + em[0];
        const float a01 = st1 + em[1];
        const float a02 = st2 + em[2];
        float aT[3];
        #pragma unroll
        for (int k = 0; k < 3; ++k)
            aT[k] = lse3(a00 + M[0][k], a01 + M[1][k], a02 + M[2][k]);
        const float denom = lse3(aT[0] + en0, aT[1] + en1, aT[2] + en2);
        atomicAdd(out, -(num - denom) * (1.0f / (float)BB));
    }
}

// ---------------------------------------------------------------------------
extern "C" void kernel_launch(void* const* d_in, const int* in_sizes, int n_in,
                              void* d_out, int out_size)
{
    const float* x       = (const float*)d_in[0];
    const int*   tags    = (const int*)  d_in[1];
    const int*   lengths = (const int*)  d_in[2];
    const float* W1      = (const float*)d_in[3];
    const float* b1      = (const float*)d_in[4];
    const float* W2      = (const float*)d_in[5];
    const float* b2      = (const float*)d_in[6];
    const float* trans   = (const float*)d_in[7];
    const float* start   = (const float*)d_in[8];
    const float* end     = (const float*)d_in[9];

    cudaFuncSetAttribute(fused_mlp_bf16,
                         cudaFuncAttributeMaxDynamicSharedMemorySize,
                         DYN_SMEM_BYTES);

    prep_kernel<<<dim3(DD / 32, HH / 32), dim3(32, 32)>>>(W1, (float*)d_out);
    fused_mlp_bf16<<<MM / 64, 256, DYN_SMEM_BYTES>>>(x, b1, W2, b2);
    crf_kernel<<<BB / CRF_WARPS, 32 * CRF_WARPS>>>(tags, lengths, trans, start, end,
                                                   (float*)d_out);
}